// round 3
// baseline (speedup 1.0000x reference)
#include <cuda_runtime.h>
#include <math_constants.h>

#define BATCH 8
#define CTX   4096
#define NEMB  512
#define HS    64
#define IL    1024
#define QSCALE 0.044194173824159216f   // 512^-0.5

// Scratch for q,k,v projections (static __device__ — no allocation).
__device__ float g_q[BATCH * CTX * HS];
__device__ float g_k[BATCH * CTX * HS];
__device__ float g_v[BATCH * CTX * HS];

// ---------------------------------------------------------------------------
// Fused QKV projection: [32768, 512] @ [512, 192] -> g_q, g_k, g_v
// Block tile 64 rows x 192 cols, 256 threads, 4x12 micro-tile.
// Column mapping n = cg + 16*j keeps smem W reads conflict-free and
// global writes coalesced across cg.
// ---------------------------------------------------------------------------
__global__ __launch_bounds__(256) void proj_kernel(
    const float* __restrict__ x,
    const float* __restrict__ Wq,
    const float* __restrict__ Wk,
    const float* __restrict__ Wv)
{
    __shared__ float xs[64][33];   // pad 33: 4 row-group reads hit distinct banks
    __shared__ float ws[32][192];

    const int row0 = blockIdx.x * 64;
    const int tid  = threadIdx.x;
    const int rg   = tid >> 4;     // 0..15 (4 rows each)
    const int cg   = tid & 15;     // 0..15 (12 cols each, stride 16)

    float acc[4][12];
#pragma unroll
    for (int i = 0; i < 4; i++)
#pragma unroll
        for (int j = 0; j < 12; j++) acc[i][j] = 0.0f;

    const float* Wm[3] = {Wq, Wk, Wv};

    for (int k0 = 0; k0 < NEMB; k0 += 32) {
        // load x tile 64x32 (512 float4)
#pragma unroll
        for (int t = 0; t < 2; t++) {
            int idx = tid + t * 256;
            int r = idx >> 3, c4 = idx & 7;
            float4 v = *reinterpret_cast<const float4*>(
                &x[(size_t)(row0 + r) * NEMB + k0 + c4 * 4]);
            xs[r][c4 * 4 + 0] = v.x; xs[r][c4 * 4 + 1] = v.y;
            xs[r][c4 * 4 + 2] = v.z; xs[r][c4 * 4 + 3] = v.w;
        }
        // load W tile 32x192 (1536 float4): cols [0,64)=Wq [64,128)=Wk [128,192)=Wv
#pragma unroll
        for (int t = 0; t < 6; t++) {
            int idx = tid + t * 256;
            int kk = idx / 48, n4 = idx % 48;
            int m = n4 >> 4, c4 = n4 & 15;
            float4 v = *reinterpret_cast<const float4*>(
                &Wm[m][(size_t)(k0 + kk) * HS + c4 * 4]);
            *reinterpret_cast<float4*>(&ws[kk][m * 64 + c4 * 4]) = v;
        }
        __syncthreads();

#pragma unroll
        for (int kk = 0; kk < 32; kk++) {
            float a[4];
#pragma unroll
            for (int i = 0; i < 4; i++) a[i] = xs[rg * 4 + i][kk];
            float b[12];
#pragma unroll
            for (int j = 0; j < 12; j++) b[j] = ws[kk][cg + 16 * j];
#pragma unroll
            for (int i = 0; i < 4; i++)
#pragma unroll
                for (int j = 0; j < 12; j++)
                    acc[i][j] = fmaf(a[i], b[j], acc[i][j]);
        }
        __syncthreads();
    }

    float* gout[3] = {g_q, g_k, g_v};
#pragma unroll
    for (int i = 0; i < 4; i++) {
        size_t r = (size_t)(row0 + rg * 4 + i);
#pragma unroll
        for (int j = 0; j < 12; j++) {
            int m   = j >> 2;                 // compile-time per unrolled j
            int col = cg + 16 * (j & 3);      // 0..63
            gout[m][r * HS + col] = acc[i][j];
        }
    }
}

// ---------------------------------------------------------------------------
// Flash attention with prefix-causal mask.
// Visible keys for query t: [0, max(IL, t+1)).  One CTA = (batch, 64-query
// block), 128 threads: rg = tid>>3 (4 rows), cg = tid&7 (8 cols).
// Only the diagonal key tile (j0 == q0, q0 >= IL) needs masking.
// ---------------------------------------------------------------------------
__global__ __launch_bounds__(128) void attn_kernel(float* __restrict__ out)
{
    extern __shared__ float sm[];
    float* qs_ = sm;                    // [64][65] q (pre-scaled)
    float* kt_ = qs_ + 64 * 65;         // [64][65] K transposed: kt[d][s]
    float* vs_ = kt_ + 64 * 65;         // [64][68] V (pad 68 -> float4 aligned)
    float* ps_ = vs_ + 64 * 68;         // [64][65] P (softmax probs)
#define QS(r, d) qs_[(r) * 65 + (d)]
#define KT(d, s) kt_[(d) * 65 + (s)]
#define VS(s, d) vs_[(s) * 68 + (d)]
#define PS(r, s) ps_[(r) * 65 + (s)]

    const int tid = threadIdx.x;
    const int rg  = tid >> 3;   // 0..15, rows rg*4..rg*4+3
    const int cg  = tid & 7;    // 0..7,  cols cg*8..cg*8+7

    // Reverse block order: heaviest prefixes launch first (load balance).
    const int q0 = ((int)gridDim.x - 1 - (int)blockIdx.x) * 64;
    const int b  = blockIdx.y;

    const float* qg = g_q + (size_t)b * CTX * HS;
    const float* kg = g_k + (size_t)b * CTX * HS;
    const float* vg = g_v + (size_t)b * CTX * HS;

    // Load Q tile (scaled by C^-0.5)
#pragma unroll
    for (int t = 0; t < 8; t++) {
        int idx = tid + t * 128;            // 1024 float4
        int r = idx >> 4, c4 = idx & 15;
        float4 v = *reinterpret_cast<const float4*>(&qg[(size_t)(q0 + r) * HS + c4 * 4]);
        QS(r, c4 * 4 + 0) = v.x * QSCALE;
        QS(r, c4 * 4 + 1) = v.y * QSCALE;
        QS(r, c4 * 4 + 2) = v.z * QSCALE;
        QS(r, c4 * 4 + 3) = v.w * QSCALE;
    }

    float m_i[4], l_i[4], o[4][8];
#pragma unroll
    for (int i = 0; i < 4; i++) {
        m_i[i] = -1e30f; l_i[i] = 0.0f;
#pragma unroll
        for (int j = 0; j < 8; j++) o[i][j] = 0.0f;
    }

    const int Lend = (q0 >= IL) ? (q0 + 64) : IL;

    for (int j0 = 0; j0 < Lend; j0 += 64) {
        const bool diag = (q0 >= IL) && (j0 == q0);

        // Load K (transposed) and V tiles
#pragma unroll
        for (int t = 0; t < 8; t++) {
            int idx = tid + t * 128;
            int s = idx >> 4, c4 = idx & 15;
            float4 kv = *reinterpret_cast<const float4*>(&kg[(size_t)(j0 + s) * HS + c4 * 4]);
            KT(c4 * 4 + 0, s) = kv.x; KT(c4 * 4 + 1, s) = kv.y;
            KT(c4 * 4 + 2, s) = kv.z; KT(c4 * 4 + 3, s) = kv.w;
            float4 vv = *reinterpret_cast<const float4*>(&vg[(size_t)(j0 + s) * HS + c4 * 4]);
            *reinterpret_cast<float4*>(&VS(s, c4 * 4)) = vv;
        }
        __syncthreads();

        // S = Q K^T
        float S[4][8];
#pragma unroll
        for (int i = 0; i < 4; i++)
#pragma unroll
            for (int j = 0; j < 8; j++) S[i][j] = 0.0f;

#pragma unroll 8
        for (int d = 0; d < 64; d++) {
            float a[4];
#pragma unroll
            for (int i = 0; i < 4; i++) a[i] = QS(rg * 4 + i, d);
            float bb[8];
#pragma unroll
            for (int j = 0; j < 8; j++) bb[j] = KT(d, cg * 8 + j);
#pragma unroll
            for (int i = 0; i < 4; i++)
#pragma unroll
                for (int j = 0; j < 8; j++)
                    S[i][j] = fmaf(a[i], bb[j], S[i][j]);
        }

        if (diag) {
#pragma unroll
            for (int i = 0; i < 4; i++) {
                int row = rg * 4 + i;
#pragma unroll
                for (int j = 0; j < 8; j++)
                    if (cg * 8 + j > row) S[i][j] = -1e30f;
            }
        }

        // Online softmax (row reductions across the 8 cg lanes)
#pragma unroll
        for (int i = 0; i < 4; i++) {
            float tm = S[i][0];
#pragma unroll
            for (int j = 1; j < 8; j++) tm = fmaxf(tm, S[i][j]);
            tm = fmaxf(tm, __shfl_xor_sync(0xffffffff, tm, 1));
            tm = fmaxf(tm, __shfl_xor_sync(0xffffffff, tm, 2));
            tm = fmaxf(tm, __shfl_xor_sync(0xffffffff, tm, 4));
            float m_new = fmaxf(m_i[i], tm);
            float alpha = __expf(m_i[i] - m_new);
            float rs = 0.0f;
#pragma unroll
            for (int j = 0; j < 8; j++) {
                float p = __expf(S[i][j] - m_new);
                S[i][j] = p;
                rs += p;
            }
            rs += __shfl_xor_sync(0xffffffff, rs, 1);
            rs += __shfl_xor_sync(0xffffffff, rs, 2);
            rs += __shfl_xor_sync(0xffffffff, rs, 4);
            l_i[i] = l_i[i] * alpha + rs;
            m_i[i] = m_new;
#pragma unroll
            for (int j = 0; j < 8; j++) o[i][j] *= alpha;
#pragma unroll
            for (int j = 0; j < 8; j++) PS(rg * 4 + i, cg * 8 + j) = S[i][j];
        }
        __syncthreads();

        // O += P @ V
#pragma unroll 8
        for (int s = 0; s < 64; s++) {
            float pv[4];
#pragma unroll
            for (int i = 0; i < 4; i++) pv[i] = PS(rg * 4 + i, s);
            float4 v0 = *reinterpret_cast<const float4*>(&VS(s, cg * 8));
            float4 v1 = *reinterpret_cast<const float4*>(&VS(s, cg * 8 + 4));
#pragma unroll
            for (int i = 0; i < 4; i++) {
                o[i][0] = fmaf(pv[i], v0.x, o[i][0]);
                o[i][1] = fmaf(pv[i], v0.y, o[i][1]);
                o[i][2] = fmaf(pv[i], v0.z, o[i][2]);
                o[i][3] = fmaf(pv[i], v0.w, o[i][3]);
                o[i][4] = fmaf(pv[i], v1.x, o[i][4]);
                o[i][5] = fmaf(pv[i], v1.y, o[i][5]);
                o[i][6] = fmaf(pv[i], v1.z, o[i][6]);
                o[i][7] = fmaf(pv[i], v1.w, o[i][7]);
            }
        }
        __syncthreads();
    }

    // Normalize and write output (float4, coalesced within rows)
#pragma unroll
    for (int i = 0; i < 4; i++) {
        float inv = 1.0f / l_i[i];
        size_t base = ((size_t)b * CTX + q0 + rg * 4 + i) * HS + cg * 8;
        float4 r0 = make_float4(o[i][0] * inv, o[i][1] * inv, o[i][2] * inv, o[i][3] * inv);
        float4 r1 = make_float4(o[i][4] * inv, o[i][5] * inv, o[i][6] * inv, o[i][7] * inv);
        *reinterpret_cast<float4*>(&out[base])     = r0;
        *reinterpret_cast<float4*>(&out[base + 4]) = r1;
    }
#undef QS
#undef KT
#undef VS
#undef PS
}

extern "C" void kernel_launch(void* const* d_in, const int* in_sizes, int n_in,
                              void* d_out, int out_size)
{
    (void)in_sizes; (void)n_in; (void)out_size;
    const float* x  = (const float*)d_in[0];
    const float* Wq = (const float*)d_in[1];
    const float* Wk = (const float*)d_in[2];
    const float* Wv = (const float*)d_in[3];
    float* out = (float*)d_out;

    const int ATTN_SMEM = (64 * 65 + 64 * 65 + 64 * 68 + 64 * 65) * (int)sizeof(float); // 67328 B
    cudaFuncSetAttribute(attn_kernel,
                         cudaFuncAttributeMaxDynamicSharedMemorySize, ATTN_SMEM);

    proj_kernel<<<(BATCH * CTX) / 64, 256>>>(x, Wq, Wk, Wv);

    dim3 grid(CTX / 64, BATCH);
    attn_kernel<<<grid, 128, ATTN_SMEM>>>(out);
}

// round 7
// speedup vs baseline: 1.3404x; 1.3404x over previous
#include <cuda_runtime.h>
#include <math_constants.h>

#define BATCH 8
#define CTX   4096
#define NEMB  512
#define HS    64
#define IL    1024
#define QSCALE 0.044194173824159216f   // 512^-0.5

// Scratch for q,k,v projections (static __device__ — no allocation).
__device__ float g_q[BATCH * CTX * HS];
__device__ float g_k[BATCH * CTX * HS];
__device__ float g_v[BATCH * CTX * HS];

// ---------------- packed f32x2 helpers ----------------
typedef unsigned long long ull;

__device__ __forceinline__ ull pk2(float lo, float hi) {
    ull r;
    asm("mov.b64 %0, {%1, %2};" : "=l"(r) : "f"(lo), "f"(hi));
    return r;
}
__device__ __forceinline__ ull dup2(float x) {
    ull r;
    asm("mov.b64 %0, {%1, %1};" : "=l"(r) : "f"(x));
    return r;
}
__device__ __forceinline__ void fma2(ull& d, ull a, ull b) {
    asm("fma.rn.f32x2 %0, %1, %2, %0;" : "+l"(d) : "l"(a), "l"(b));
}
__device__ __forceinline__ void mul2(ull& d, ull a) {
    asm("mul.rn.f32x2 %0, %0, %1;" : "+l"(d) : "l"(a));
}
__device__ __forceinline__ float2 up2(ull v) {
    float2 f;
    asm("mov.b64 {%0, %1}, %2;" : "=f"(f.x), "=f"(f.y) : "l"(v));
    return f;
}

// ---------------------------------------------------------------------------
// Fused QKV projection: [32768, 512] @ [512, 192] -> g_q, g_k, g_v
// Block tile 64 rows x 192 cols, 256 threads. Each thread: 4 rows x 12 cols,
// cols = {m*64 + cg*4 .. +3} for m in {0,1,2}; accumulators packed f32x2.
// ---------------------------------------------------------------------------
__global__ __launch_bounds__(256) void proj_kernel(
    const float* __restrict__ x,
    const float* __restrict__ Wq,
    const float* __restrict__ Wk,
    const float* __restrict__ Wv)
{
    __shared__ float xs[64][36];   // pad 36: float4-aligned, conflict-free
    __shared__ float ws[32][192];

    const int row0 = blockIdx.x * 64;
    const int tid  = threadIdx.x;
    const int rg   = tid >> 4;     // 0..15 (4 rows each)
    const int cg   = tid & 15;     // 0..15 (4 cols per matrix)

    ull acc2[4][6];
#pragma unroll
    for (int i = 0; i < 4; i++)
#pragma unroll
        for (int p = 0; p < 6; p++) acc2[i][p] = 0ULL;

    const float* Wm[3] = {Wq, Wk, Wv};

    for (int k0 = 0; k0 < NEMB; k0 += 32) {
        // load x tile 64x32 (512 float4)
#pragma unroll
        for (int t = 0; t < 2; t++) {
            int idx = tid + t * 256;
            int r = idx >> 3, c4 = idx & 7;
            float4 v = *reinterpret_cast<const float4*>(
                &x[(size_t)(row0 + r) * NEMB + k0 + c4 * 4]);
            *reinterpret_cast<float4*>(&xs[r][c4 * 4]) = v;
        }
        // load W tile 32x192: cols [0,64)=Wq [64,128)=Wk [128,192)=Wv
#pragma unroll
        for (int t = 0; t < 6; t++) {
            int idx = tid + t * 256;
            int kk = idx / 48, n4 = idx % 48;
            int m = n4 >> 4, c4 = n4 & 15;
            float4 v = *reinterpret_cast<const float4*>(
                &Wm[m][(size_t)(k0 + kk) * HS + c4 * 4]);
            *reinterpret_cast<float4*>(&ws[kk][m * 64 + c4 * 4]) = v;
        }
        __syncthreads();

#pragma unroll
        for (int kk0 = 0; kk0 < 32; kk0 += 4) {
            float av[4][4];
#pragma unroll
            for (int i = 0; i < 4; i++) {
                float4 a4 = *reinterpret_cast<const float4*>(&xs[rg * 4 + i][kk0]);
                av[i][0] = a4.x; av[i][1] = a4.y; av[i][2] = a4.z; av[i][3] = a4.w;
            }
#pragma unroll
            for (int dd = 0; dd < 4; dd++) {
                int kk = kk0 + dd;
                float4 b0 = *reinterpret_cast<const float4*>(&ws[kk][cg * 4]);
                float4 b1 = *reinterpret_cast<const float4*>(&ws[kk][64 + cg * 4]);
                float4 b2 = *reinterpret_cast<const float4*>(&ws[kk][128 + cg * 4]);
                ull bp[6] = {pk2(b0.x, b0.y), pk2(b0.z, b0.w),
                             pk2(b1.x, b1.y), pk2(b1.z, b1.w),
                             pk2(b2.x, b2.y), pk2(b2.z, b2.w)};
#pragma unroll
                for (int i = 0; i < 4; i++) {
                    ull ad = dup2(av[i][dd]);
#pragma unroll
                    for (int p = 0; p < 6; p++) fma2(acc2[i][p], ad, bp[p]);
                }
            }
        }
        __syncthreads();
    }

    float* gout[3] = {g_q, g_k, g_v};
#pragma unroll
    for (int i = 0; i < 4; i++) {
        size_t r = (size_t)(row0 + rg * 4 + i);
#pragma unroll
        for (int m = 0; m < 3; m++) {
            float2 lo = up2(acc2[i][m * 2]);
            float2 hi = up2(acc2[i][m * 2 + 1]);
            float4 v = make_float4(lo.x, lo.y, hi.x, hi.y);
            *reinterpret_cast<float4*>(&gout[m][r * HS + cg * 4]) = v;
        }
    }
}

// ---------------------------------------------------------------------------
// Flash attention with prefix-causal mask. Visible keys for query t:
// [0, max(IL, t+1)).  One CTA = (batch, 64-query block), 128 threads:
// rg = tid>>3 (4 rows), cg = tid&7.  Each thread's 8 key-columns are the
// two conflict-free float4 groups {cg*4..+3} and {32+cg*4..+3}.
// Accumulators packed f32x2 (fma.rn.f32x2).  smem 68 KB -> 3 CTAs/SM.
// ---------------------------------------------------------------------------
__global__ __launch_bounds__(128) void attn_kernel(float* __restrict__ out)
{
    extern __shared__ float sm[];
    float* qs_ = sm;                    // [64][68] q (pre-scaled)
    float* kt_ = qs_ + 64 * 68;         // [64][68] K transposed: kt[d][s]
    float* vs_ = kt_ + 64 * 68;         // [64][68] V
    float* ps_ = vs_ + 64 * 68;         // [64][68] P (softmax probs)
#define QS(r, d) qs_[(r) * 68 + (d)]
#define KT(d, s) kt_[(d) * 68 + (s)]
#define VS(s, d) vs_[(s) * 68 + (d)]
#define PS(r, s) ps_[(r) * 68 + (s)]

    const int tid = threadIdx.x;
    const int rg  = tid >> 3;   // 0..15, rows rg*4..rg*4+3
    const int cg  = tid & 7;    // 0..7

    // Reverse block order: heaviest prefixes launch first (load balance).
    const int q0 = ((int)gridDim.x - 1 - (int)blockIdx.x) * 64;
    const int b  = blockIdx.y;

    const float* qg = g_q + (size_t)b * CTX * HS;
    const float* kg = g_k + (size_t)b * CTX * HS;
    const float* vg = g_v + (size_t)b * CTX * HS;

    // Load Q tile (scaled by C^-0.5)
#pragma unroll
    for (int t = 0; t < 8; t++) {
        int idx = tid + t * 128;            // 1024 float4
        int r = idx >> 4, c4 = idx & 15;
        float4 v = *reinterpret_cast<const float4*>(&qg[(size_t)(q0 + r) * HS + c4 * 4]);
        QS(r, c4 * 4 + 0) = v.x * QSCALE;
        QS(r, c4 * 4 + 1) = v.y * QSCALE;
        QS(r, c4 * 4 + 2) = v.z * QSCALE;
        QS(r, c4 * 4 + 3) = v.w * QSCALE;
    }

    float m_i[4], l_i[4];
    ull o2[4][4];
#pragma unroll
    for (int i = 0; i < 4; i++) {
        m_i[i] = -1e30f; l_i[i] = 0.0f;
#pragma unroll
        for (int p = 0; p < 4; p++) o2[i][p] = 0ULL;
    }

    const int Lend = (q0 >= IL) ? (q0 + 64) : IL;

    for (int j0 = 0; j0 < Lend; j0 += 64) {
        const bool diag = (q0 >= IL) && (j0 == q0);

        // Load K (transposed) and V tiles
#pragma unroll
        for (int t = 0; t < 8; t++) {
            int idx = tid + t * 128;
            int s = idx >> 4, c4 = idx & 15;
            float4 kv = *reinterpret_cast<const float4*>(&kg[(size_t)(j0 + s) * HS + c4 * 4]);
            KT(c4 * 4 + 0, s) = kv.x; KT(c4 * 4 + 1, s) = kv.y;
            KT(c4 * 4 + 2, s) = kv.z; KT(c4 * 4 + 3, s) = kv.w;
            float4 vv = *reinterpret_cast<const float4*>(&vg[(size_t)(j0 + s) * HS + c4 * 4]);
            *reinterpret_cast<float4*>(&VS(s, c4 * 4)) = vv;
        }
        __syncthreads();

        // S = Q K^T  (packed accumulators: 4 rows x 4 col-pairs)
        ull S2[4][4];
#pragma unroll
        for (int i = 0; i < 4; i++)
#pragma unroll
            for (int p = 0; p < 4; p++) S2[i][p] = 0ULL;

#pragma unroll 4
        for (int d0 = 0; d0 < 64; d0 += 4) {
            float av[4][4];
#pragma unroll
            for (int i = 0; i < 4; i++) {
                float4 a4 = *reinterpret_cast<const float4*>(&QS(rg * 4 + i, d0));
                av[i][0] = a4.x; av[i][1] = a4.y; av[i][2] = a4.z; av[i][3] = a4.w;
            }
#pragma unroll
            for (int dd = 0; dd < 4; dd++) {
                float4 k0 = *reinterpret_cast<const float4*>(&KT(d0 + dd, cg * 4));
                float4 k1 = *reinterpret_cast<const float4*>(&KT(d0 + dd, 32 + cg * 4));
                ull kb[4] = {pk2(k0.x, k0.y), pk2(k0.z, k0.w),
                             pk2(k1.x, k1.y), pk2(k1.z, k1.w)};
#pragma unroll
                for (int i = 0; i < 4; i++) {
                    ull ad = dup2(av[i][dd]);
#pragma unroll
                    for (int p = 0; p < 4; p++) fma2(S2[i][p], ad, kb[p]);
                }
            }
        }

        // Softmax (online). Unpack S2 -> S[8]; cols: j<4 -> cg*4+j, else 32+cg*4+j-4
#pragma unroll
        for (int i = 0; i < 4; i++) {
            float S[8];
            {
                float2 p0 = up2(S2[i][0]), p1 = up2(S2[i][1]);
                float2 p2 = up2(S2[i][2]), p3 = up2(S2[i][3]);
                S[0] = p0.x; S[1] = p0.y; S[2] = p1.x; S[3] = p1.y;
                S[4] = p2.x; S[5] = p2.y; S[6] = p3.x; S[7] = p3.y;
            }
            if (diag) {
                int row = rg * 4 + i;
#pragma unroll
                for (int j = 0; j < 8; j++) {
                    int c = (j < 4) ? (cg * 4 + j) : (32 + cg * 4 + j - 4);
                    if (c > row) S[j] = -1e30f;
                }
            }
            float tm = S[0];
#pragma unroll
            for (int j = 1; j < 8; j++) tm = fmaxf(tm, S[j]);
            tm = fmaxf(tm, __shfl_xor_sync(0xffffffff, tm, 1));
            tm = fmaxf(tm, __shfl_xor_sync(0xffffffff, tm, 2));
            tm = fmaxf(tm, __shfl_xor_sync(0xffffffff, tm, 4));
            float m_new = fmaxf(m_i[i], tm);
            float alpha = __expf(m_i[i] - m_new);
            float rs = 0.0f;
#pragma unroll
            for (int j = 0; j < 8; j++) {
                float p = __expf(S[j] - m_new);
                S[j] = p;
                rs += p;
            }
            rs += __shfl_xor_sync(0xffffffff, rs, 1);
            rs += __shfl_xor_sync(0xffffffff, rs, 2);
            rs += __shfl_xor_sync(0xffffffff, rs, 4);
            l_i[i] = l_i[i] * alpha + rs;
            m_i[i] = m_new;
            ull ad = dup2(alpha);
#pragma unroll
            for (int p = 0; p < 4; p++) mul2(o2[i][p], ad);

            int row = rg * 4 + i;
            *reinterpret_cast<float4*>(&PS(row, cg * 4))      = make_float4(S[0], S[1], S[2], S[3]);
            *reinterpret_cast<float4*>(&PS(row, 32 + cg * 4)) = make_float4(S[4], S[5], S[6], S[7]);
        }
        __syncthreads();

        // O += P @ V  (packed)
#pragma unroll 4
        for (int s0 = 0; s0 < 64; s0 += 4) {
            float pv[4][4];
#pragma unroll
            for (int i = 0; i < 4; i++) {
                float4 p4 = *reinterpret_cast<const float4*>(&PS(rg * 4 + i, s0));
                pv[i][0] = p4.x; pv[i][1] = p4.y; pv[i][2] = p4.z; pv[i][3] = p4.w;
            }
#pragma unroll
            for (int ss = 0; ss < 4; ss++) {
                float4 v0 = *reinterpret_cast<const float4*>(&VS(s0 + ss, cg * 4));
                float4 v1 = *reinterpret_cast<const float4*>(&VS(s0 + ss, 32 + cg * 4));
                ull vb[4] = {pk2(v0.x, v0.y), pk2(v0.z, v0.w),
                             pk2(v1.x, v1.y), pk2(v1.z, v1.w)};
#pragma unroll
                for (int i = 0; i < 4; i++) {
                    ull pd = dup2(pv[i][ss]);
#pragma unroll
                    for (int p = 0; p < 4; p++) fma2(o2[i][p], pd, vb[p]);
                }
            }
        }
        __syncthreads();
    }

    // Normalize and write output: cols cg*4..+3 and 32+cg*4..+3
#pragma unroll
    for (int i = 0; i < 4; i++) {
        float inv = 1.0f / l_i[i];
        size_t base = ((size_t)b * CTX + q0 + rg * 4 + i) * HS;
        float2 a0 = up2(o2[i][0]), a1 = up2(o2[i][1]);
        float2 a2 = up2(o2[i][2]), a3 = up2(o2[i][3]);
        float4 r0 = make_float4(a0.x * inv, a0.y * inv, a1.x * inv, a1.y * inv);
        float4 r1 = make_float4(a2.x * inv, a2.y * inv, a3.x * inv, a3.y * inv);
        *reinterpret_cast<float4*>(&out[base + cg * 4])      = r0;
        *reinterpret_cast<float4*>(&out[base + 32 + cg * 4]) = r1;
    }
#undef QS
#undef KT
#undef VS
#undef PS
}

extern "C" void kernel_launch(void* const* d_in, const int* in_sizes, int n_in,
                              void* d_out, int out_size)
{
    (void)in_sizes; (void)n_in; (void)out_size;
    const float* x  = (const float*)d_in[0];
    const float* Wq = (const float*)d_in[1];
    const float* Wk = (const float*)d_in[2];
    const float* Wv = (const float*)d_in[3];
    float* out = (float*)d_out;

    const int ATTN_SMEM = 4 * 64 * 68 * (int)sizeof(float); // 69632 B -> 3 CTAs/SM
    cudaFuncSetAttribute(attn_kernel,
                         cudaFuncAttributeMaxDynamicSharedMemorySize, ATTN_SMEM);

    proj_kernel<<<(BATCH * CTX) / 64, 256>>>(x, Wq, Wk, Wv);

    dim3 grid(CTX / 64, BATCH);
    attn_kernel<<<grid, 128, ATTN_SMEM>>>(out);
}